// round 14
// baseline (speedup 1.0000x reference)
#include <cuda_runtime.h>
#include <cuda_fp16.h>
#include <cstdint>

// ---------------------------------------------------------------------------
// Problem dims
// ---------------------------------------------------------------------------
#define BB   64
#define NSET 512
#define DIN  512
#define DH   1024
#define MPHI (BB * NSET)   // 32768

// GEMM tiling: CTA 128x256, BK=64, warp tile 64x64 (2x4 warps), 4 stages
#define BM 128
#define BN 256
#define BK 64
#define OFFB 16384
#define STG  49152
#define NSTAGE 4
#define DYN_SMEM (NSTAGE * STG + 1024)

// ---------------------------------------------------------------------------
// Device scratch (fp16 words as unsigned short)
// ---------------------------------------------------------------------------
__device__ unsigned short g_x16[(size_t)MPHI * DIN];     // x as fp16
__device__ unsigned short g_w1t[(size_t)DH * DIN];       // W1^T [N,K] fp16
__device__ unsigned short g_w2t[(size_t)DH * DH];        // W2^T [N,K] fp16
__device__ unsigned short g_h1[(size_t)MPHI * DH];       // h1 fp16
__device__ float g_pooled[BB * 2 * DH];
__device__ float g_racc1[BB * DH];
__device__ float g_racc2[BB * DH];

// ---------------------------------------------------------------------------
// PTX helpers
// ---------------------------------------------------------------------------
__device__ __forceinline__ uint32_t smem_u32(const void* p) {
    uint32_t a;
    asm("{ .reg .u64 t; cvta.to.shared.u64 t, %1; cvt.u32.u64 %0, t; }"
        : "=r"(a) : "l"(p));
    return a;
}

__device__ __forceinline__ void cp16(uint32_t dst, const void* src) {
    asm volatile("cp.async.cg.shared.global [%0], [%1], 16;"
                 :: "r"(dst), "l"(src));
}
#define CP_COMMIT() asm volatile("cp.async.commit_group;" ::: "memory")
#define CP_WAIT(n)  asm volatile("cp.async.wait_group %0;" :: "n"(n) : "memory")

__device__ __forceinline__ void ldsm_x4(uint32_t& r0, uint32_t& r1,
                                        uint32_t& r2, uint32_t& r3, uint32_t addr) {
    asm volatile("ldmatrix.sync.aligned.m8n8.x4.shared.b16 {%0,%1,%2,%3}, [%4];"
                 : "=r"(r0), "=r"(r1), "=r"(r2), "=r"(r3) : "r"(addr));
}

__device__ __forceinline__ void mma16816(float* c, const uint32_t* a, const uint32_t* b) {
    asm volatile(
        "mma.sync.aligned.m16n8k16.row.col.f32.f16.f16.f32 "
        "{%0,%1,%2,%3}, {%4,%5,%6,%7}, {%8,%9}, {%0,%1,%2,%3};"
        : "+f"(c[0]), "+f"(c[1]), "+f"(c[2]), "+f"(c[3])
        : "r"(a[0]), "r"(a[1]), "r"(a[2]), "r"(a[3]), "r"(b[0]), "r"(b[1]));
}

__device__ __forceinline__ uint32_t pack_h2(float v0, float v1) {
    __half h0 = __float2half_rn(v0);
    __half h1 = __float2half_rn(v1);
    return ((uint32_t)__half_as_ushort(h1) << 16) | (uint32_t)__half_as_ushort(h0);
}

// ---------------------------------------------------------------------------
// Pure fp16 HMMA GEMM, 4-stage cp.async pipeline (at legacy-HMMA HW floor).
// MODE 0 (layer1): A = x16, B = W1t; epilogue stores h1 fp16.
// MODE 1 (layer2): A = h1,  B = W2t; epilogue fuses sum/max pooling.
// (UNCHANGED — proven correct and at floor.)
// ---------------------------------------------------------------------------
template <int MODE>
__global__ void __launch_bounds__(256, 1)
phi_gemm(const float* __restrict__ bias, int K, int C)
{
    extern __shared__ char dsm[];
    __shared__ float sbias[BN];
    __shared__ float sSum[2][BN], sMax[2][BN];

    const int tid  = threadIdx.x;
    const int lane = tid & 31;
    const int wid  = tid >> 5;
    const int wm   = wid >> 2;     // 0..1
    const int wn   = wid & 3;      // 0..3
    const int rowBlk = blockIdx.y * BM;
    const int colBlk = blockIdx.x * BN;

    const unsigned short* A = (MODE == 0) ? g_x16 : g_h1;
    const unsigned short* Bm = (MODE == 0) ? g_w1t : g_w2t;

    const uint32_t sb = (smem_u32(dsm) + 1023u) & ~1023u;

    if (tid < BN) sbias[tid] = bias[colBlk + tid];

    float acc[4][8][4];
#pragma unroll
    for (int i = 0; i < 4; i++)
#pragma unroll
        for (int j = 0; j < 8; j++)
#pragma unroll
            for (int k = 0; k < 4; k++) acc[i][j][k] = 0.f;

    // ldmatrix per-thread addressing (swizzled 128B rows)
    const int arow = wm * 64 + (lane & 15);
    const uint32_t aRowOff = (uint32_t)arow * 128;
    const uint32_t aXor = ((uint32_t)(arow & 7)) << 4;
    const int brow = wn * 64 + (lane & 15);
    const uint32_t bRowOff = (uint32_t)brow * 128;
    const uint32_t bXor = ((uint32_t)(brow & 7)) << 4;
    const uint32_t csel = ((uint32_t)((lane >> 4) & 1)) << 4;

    auto load_chunk = [&](int stage, int kt) {
        uint32_t st = sb + stage * STG;
#pragma unroll
        for (int l = 0; l < 4; l++) {
            int f = tid + l * 256;
            int r = f >> 3, q = f & 7;
            uint32_t off = (uint32_t)(r * 128) +
                           (((uint32_t)(q * 16)) ^ (((uint32_t)(r & 7)) << 4));
            cp16(st + off, A + (size_t)(rowBlk + r) * K + kt + q * 8);
        }
#pragma unroll
        for (int l = 0; l < 8; l++) {
            int f = tid + l * 256;
            int r = f >> 3, q = f & 7;
            uint32_t off = (uint32_t)(r * 128) +
                           (((uint32_t)(q * 16)) ^ (((uint32_t)(r & 7)) << 4));
            cp16(st + OFFB + off, Bm + (size_t)(colBlk + r) * K + kt + q * 8);
        }
        CP_COMMIT();
    };

    load_chunk(0, 0);
    if (C > 1) load_chunk(1, BK);
    if (C > 2) load_chunk(2, 2 * BK);

    for (int c = 0; c < C; c++) {
        if (c + 2 < C)      { CP_WAIT(2); }
        else if (c + 1 < C) { CP_WAIT(1); }
        else                { CP_WAIT(0); }
        __syncthreads();
        if (c + 3 < C) load_chunk((c + 3) & (NSTAGE - 1), (c + 3) * BK);

        const uint32_t st = sb + (c & (NSTAGE - 1)) * STG;
#pragma unroll
        for (int k16 = 0; k16 < 4; k16++) {
            const uint32_t cb = k16 * 32;
            uint32_t ah[4][4];
#pragma unroll
            for (int mi = 0; mi < 4; mi++) {
                uint32_t aoff = aRowOff + mi * 2048 + ((cb + csel) ^ aXor);
                ldsm_x4(ah[mi][0], ah[mi][1], ah[mi][2], ah[mi][3], st + aoff);
            }
#pragma unroll
            for (int nb = 0; nb < 4; nb++) {
                uint32_t boff = bRowOff + nb * 2048 + ((cb + csel) ^ bXor);
                uint32_t b0, b1, b2, b3;
                ldsm_x4(b0, b1, b2, b3, st + OFFB + boff);
                uint32_t bfr0[2] = {b0, b2};
                uint32_t bfr1[2] = {b1, b3};
#pragma unroll
                for (int mi = 0; mi < 4; mi++) {
                    mma16816(acc[mi][nb * 2],     ah[mi], bfr0);
                    mma16816(acc[mi][nb * 2 + 1], ah[mi], bfr1);
                }
            }
        }
    }

    // ------------------------- epilogue -------------------------
    const int r0base = wm * 64 + (lane >> 2);
    const int n0base = wn * 64 + 2 * (lane & 3);

    if (MODE == 0) {
#pragma unroll
        for (int mi = 0; mi < 4; mi++) {
            int r0 = rowBlk + r0base + mi * 16;
#pragma unroll
            for (int ni = 0; ni < 8; ni++) {
                int nrel = n0base + ni * 8;
                float b0 = sbias[nrel], b1 = sbias[nrel + 1];
                float v00 = fmaxf(acc[mi][ni][0] + b0, 0.f);
                float v01 = fmaxf(acc[mi][ni][1] + b1, 0.f);
                float v10 = fmaxf(acc[mi][ni][2] + b0, 0.f);
                float v11 = fmaxf(acc[mi][ni][3] + b1, 0.f);
                *(uint32_t*)&g_h1[(size_t)r0 * DH + colBlk + nrel] = pack_h2(v00, v01);
                *(uint32_t*)&g_h1[(size_t)(r0 + 8) * DH + colBlk + nrel] = pack_h2(v10, v11);
            }
        }
    } else {
        const int bIdx = rowBlk >> 9;
        float s[8][2], mx[8][2];
#pragma unroll
        for (int ni = 0; ni < 8; ni++) { s[ni][0] = s[ni][1] = 0.f;
                                         mx[ni][0] = mx[ni][1] = 0.f; }
#pragma unroll
        for (int mi = 0; mi < 4; mi++)
#pragma unroll
            for (int ni = 0; ni < 8; ni++) {
                int nrel = n0base + ni * 8;
                float b0 = sbias[nrel], b1 = sbias[nrel + 1];
                float v00 = fmaxf(acc[mi][ni][0] + b0, 0.f);
                float v01 = fmaxf(acc[mi][ni][1] + b1, 0.f);
                float v10 = fmaxf(acc[mi][ni][2] + b0, 0.f);
                float v11 = fmaxf(acc[mi][ni][3] + b1, 0.f);
                s[ni][0] += v00 + v10;  s[ni][1] += v01 + v11;
                mx[ni][0] = fmaxf(mx[ni][0], fmaxf(v00, v10));
                mx[ni][1] = fmaxf(mx[ni][1], fmaxf(v01, v11));
            }
#pragma unroll
        for (int o = 4; o < 32; o <<= 1)
#pragma unroll
            for (int ni = 0; ni < 8; ni++)
#pragma unroll
                for (int j = 0; j < 2; j++) {
                    s[ni][j]  += __shfl_xor_sync(0xffffffffu, s[ni][j], o);
                    mx[ni][j]  = fmaxf(mx[ni][j],
                                       __shfl_xor_sync(0xffffffffu, mx[ni][j], o));
                }
        if ((lane >> 2) == 0) {
#pragma unroll
            for (int ni = 0; ni < 8; ni++)
#pragma unroll
                for (int j = 0; j < 2; j++) {
                    int col = wn * 64 + ni * 8 + 2 * lane + j;
                    sSum[wm][col] = s[ni][j];
                    sMax[wm][col] = mx[ni][j];
                }
        }
        __syncthreads();
        {
            float S = sSum[0][tid] + sSum[1][tid];
            float M = fmaxf(sMax[0][tid], sMax[1][tid]);
            atomicAdd(&g_pooled[bIdx * 2 * DH + colBlk + tid], S);
            atomicMax((int*)&g_pooled[bIdx * 2 * DH + DH + colBlk + tid],
                      __float_as_int(M));
        }
    }
}

// ---------------------------------------------------------------------------
// Fused prep kernel (cvt at 32B/thread: 8192 cvt blocks)
// ---------------------------------------------------------------------------
#define PREP_CVT_BLKS 8192    // MPHI*DIN/8/256 (2 float4 per thread)
#define PREP_Z_BLKS   512
#define PREP_T1_BLKS  512     // (DH/32)*(DIN/32)
#define PREP_T2_BLKS  1024    // (DH/32)*(DH/32)
#define PREP_BLKS (PREP_CVT_BLKS + PREP_Z_BLKS + PREP_T1_BLKS + PREP_T2_BLKS)

__global__ void __launch_bounds__(256)
prep_kernel(const float* __restrict__ x,
            const float* __restrict__ W1,
            const float* __restrict__ W2)
{
    __shared__ float t[32][33];
    const int b = blockIdx.x;
    const int tid = threadIdx.x;

    if (b < PREP_CVT_BLKS) {
        int i = (b * 256 + tid) * 2;               // float4 index (2 per thread)
#pragma unroll
        for (int u = 0; u < 2; u++) {
            float4 v = ((const float4*)x)[i + u];
            uint2 o;
            o.x = pack_h2(v.x, v.y);
            o.y = pack_h2(v.z, v.w);
            ((uint2*)g_x16)[i + u] = o;
        }
        return;
    }
    if (b < PREP_CVT_BLKS + PREP_Z_BLKS) {
        int i = (b - PREP_CVT_BLKS) * 256 + tid;
        if (i < BB * 2 * DH) g_pooled[i] = 0.f;
        if (i < BB * DH) { g_racc1[i] = 0.f; g_racc2[i] = 0.f; }
        return;
    }
    const float* src;
    unsigned short* dst;
    int R, Cn, bb;
    if (b < PREP_CVT_BLKS + PREP_Z_BLKS + PREP_T1_BLKS) {
        bb = b - (PREP_CVT_BLKS + PREP_Z_BLKS);
        src = W1; dst = g_w1t; R = DIN; Cn = DH;
    } else {
        bb = b - (PREP_CVT_BLKS + PREP_Z_BLKS + PREP_T1_BLKS);
        src = W2; dst = g_w2t; R = DH; Cn = DH;
    }
    const int bx = (bb & 31) * 32;
    const int by = (bb >> 5) * 32;
    const int tx = tid & 31, ty = tid >> 5;
#pragma unroll
    for (int i = 0; i < 32; i += 8)
        t[ty + i][tx] = src[(size_t)(by + ty + i) * Cn + bx + tx];
    __syncthreads();
#pragma unroll
    for (int i = 0; i < 32; i += 8) {
        int n = bx + ty + i, k = by + tx;
        dst[(size_t)n * R + k] = __half_as_ushort(__float2half_rn(t[tx][ty + i]));
    }
}

// ---------------------------------------------------------------------------
// rho GEMMs: split-K FFMA, 4x4 register blocking, KS=64 (single k-tile per
// CTA — latency-bound fix: 2x the CTAs, half the serial critical path).
// Tile: 64 rows (all of M) x 64 cols x 64 k per CTA.
// PHASE 0: A = g_pooled (lda 2048) -> g_racc1.  grid (16, 32)
// PHASE 1: A = relu(g_racc1 + br1) on load (lda 1024) -> g_racc2. grid (16, 16)
// ---------------------------------------------------------------------------
template <int PHASE>
__global__ void __launch_bounds__(256)
rho_partial(const float* __restrict__ W, const float* __restrict__ bias_in)
{
    const int lda = (PHASE == 0) ? 2 * DH : DH;
    const float* A = (PHASE == 0) ? (const float*)g_pooled : (const float*)g_racc1;
    float* acc     = (PHASE == 0) ? g_racc1 : g_racc2;

    __shared__ float As[64][68];   // [kk][row], 272B rows (16B aligned)
    __shared__ float Ws[64][68];   // [kk][col]

    const int tid = threadIdx.x;
    const int tx = tid & 15, ty = tid >> 4;    // 16 x 16
    const int col0 = blockIdx.x * 64;
    const int kbase = blockIdx.y * 64;

    float a16[4][4];
#pragma unroll
    for (int i = 0; i < 4; i++)
#pragma unroll
        for (int j = 0; j < 4; j++) a16[i][j] = 0.f;

    // load A slice [64 rows x 64 k], transposed to As[kk][row]
#pragma unroll
    for (int l = 0; l < 4; l++) {
        int f = tid + l * 256;             // 0..1023 (float4 units)
        int row = f >> 4, kq = f & 15;
        float4 v = *reinterpret_cast<const float4*>(
            &A[(size_t)row * lda + kbase + kq * 4]);
        if (PHASE == 1) {
            float4 bv = *reinterpret_cast<const float4*>(&bias_in[kbase + kq * 4]);
            v.x = fmaxf(v.x + bv.x, 0.f); v.y = fmaxf(v.y + bv.y, 0.f);
            v.z = fmaxf(v.z + bv.z, 0.f); v.w = fmaxf(v.w + bv.w, 0.f);
        }
        As[kq * 4 + 0][row] = v.x; As[kq * 4 + 1][row] = v.y;
        As[kq * 4 + 2][row] = v.z; As[kq * 4 + 3][row] = v.w;
    }
    // load W slice [64 k x 64 cols] to Ws[kk][col]
#pragma unroll
    for (int l = 0; l < 4; l++) {
        int f = tid + l * 256;
        int kk = f >> 4, cq = f & 15;
        float4 v = *reinterpret_cast<const float4*>(
            &W[(size_t)(kbase + kk) * DH + col0 + cq * 4]);
        *reinterpret_cast<float4*>(&Ws[kk][cq * 4]) = v;
    }
    __syncthreads();
#pragma unroll
    for (int kk = 0; kk < 64; kk++) {
        float4 av = *reinterpret_cast<const float4*>(&As[kk][ty * 4]);
        float4 wv = *reinterpret_cast<const float4*>(&Ws[kk][tx * 4]);
        float avr[4] = {av.x, av.y, av.z, av.w};
        float wvr[4] = {wv.x, wv.y, wv.z, wv.w};
#pragma unroll
        for (int i = 0; i < 4; i++)
#pragma unroll
            for (int j = 0; j < 4; j++) a16[i][j] += avr[i] * wvr[j];
    }

#pragma unroll
    for (int i = 0; i < 4; i++)
#pragma unroll
        for (int j = 0; j < 4; j++)
            atomicAdd(&acc[(size_t)(ty * 4 + i) * DH + col0 + tx * 4 + j], a16[i][j]);
}

// final: out = relu(g_racc2 + br2)
__global__ void bias_relu_final(const float* __restrict__ b, float* __restrict__ out) {
    int i = blockIdx.x * 256 + threadIdx.x;
    out[i] = fmaxf(g_racc2[i] + b[i & (DH - 1)], 0.f);
}

// ---------------------------------------------------------------------------
// Launch
// ---------------------------------------------------------------------------
extern "C" void kernel_launch(void* const* d_in, const int* in_sizes, int n_in,
                              void* d_out, int out_size)
{
    const float* x   = (const float*)d_in[0];
    const float* W1  = (const float*)d_in[1];
    const float* b1  = (const float*)d_in[2];
    const float* W2  = (const float*)d_in[3];
    const float* b2  = (const float*)d_in[4];
    const float* Wr1 = (const float*)d_in[5];
    const float* br1 = (const float*)d_in[6];
    const float* Wr2 = (const float*)d_in[7];
    const float* br2 = (const float*)d_in[8];
    float* out       = (float*)d_out;

    cudaFuncSetAttribute(phi_gemm<0>, cudaFuncAttributeMaxDynamicSharedMemorySize, DYN_SMEM);
    cudaFuncSetAttribute(phi_gemm<1>, cudaFuncAttributeMaxDynamicSharedMemorySize, DYN_SMEM);

    // fused prep: cvt x, zero accumulators, transpose+cvt W1/W2
    prep_kernel<<<PREP_BLKS, 256>>>(x, W1, W2);

    // phi layer 1: h1 = relu(x @ W1 + b1) -> fp16
    phi_gemm<0><<<dim3(DH / BN, MPHI / BM), 256, DYN_SMEM>>>(b1, DIN, DIN / BK);
    // phi layer 2 + fused sum/max pooling
    phi_gemm<1><<<dim3(DH / BN, MPHI / BM), 256, DYN_SMEM>>>(b2, DH, DH / BK);

    // rho (fp32 exact): 64x64x64 tiles, one k-tile per CTA
    rho_partial<0><<<dim3(DH / 64, 2 * DH / 64), 256>>>(Wr1, nullptr);  // 512 CTAs
    rho_partial<1><<<dim3(DH / 64, DH / 64),     256>>>(Wr2, br1);      // 256 CTAs
    bias_relu_final<<<BB * DH / 256, 256>>>(br2, out);
}

// round 15
// speedup vs baseline: 1.0042x; 1.0042x over previous
#include <cuda_runtime.h>
#include <cuda_fp16.h>
#include <cstdint>

// ---------------------------------------------------------------------------
// Problem dims
// ---------------------------------------------------------------------------
#define BB   64
#define NSET 512
#define DIN  512
#define DH   1024
#define MPHI (BB * NSET)   // 32768

// GEMM tiling: CTA 128x256, BK=64, warp tile 64x64 (2x4 warps), 4 stages
#define BM 128
#define BN 256
#define BK 64
#define OFFB 16384
#define STG  49152
#define NSTAGE 4
#define DYN_SMEM (NSTAGE * STG + 1024)

// rho smem: 2 bufs x (As 64x68 + Ws 64x68) floats
#define RHO_TILE (64 * 68)
#define RHO_SMEM (4 * RHO_TILE * (int)sizeof(float))   // 69632 B

// ---------------------------------------------------------------------------
// Device scratch (fp16 words as unsigned short)
// ---------------------------------------------------------------------------
__device__ unsigned short g_x16[(size_t)MPHI * DIN];     // x as fp16
__device__ unsigned short g_w1t[(size_t)DH * DIN];       // W1^T [N,K] fp16
__device__ unsigned short g_w2t[(size_t)DH * DH];        // W2^T [N,K] fp16
__device__ unsigned short g_h1[(size_t)MPHI * DH];       // h1 fp16
__device__ float g_pooled[BB * 2 * DH];
__device__ float g_racc1[BB * DH];
__device__ float g_racc2[BB * DH];

// ---------------------------------------------------------------------------
// PTX helpers
// ---------------------------------------------------------------------------
__device__ __forceinline__ uint32_t smem_u32(const void* p) {
    uint32_t a;
    asm("{ .reg .u64 t; cvta.to.shared.u64 t, %1; cvt.u32.u64 %0, t; }"
        : "=r"(a) : "l"(p));
    return a;
}

__device__ __forceinline__ void cp16(uint32_t dst, const void* src) {
    asm volatile("cp.async.cg.shared.global [%0], [%1], 16;"
                 :: "r"(dst), "l"(src));
}
#define CP_COMMIT() asm volatile("cp.async.commit_group;" ::: "memory")
#define CP_WAIT(n)  asm volatile("cp.async.wait_group %0;" :: "n"(n) : "memory")

__device__ __forceinline__ void ldsm_x4(uint32_t& r0, uint32_t& r1,
                                        uint32_t& r2, uint32_t& r3, uint32_t addr) {
    asm volatile("ldmatrix.sync.aligned.m8n8.x4.shared.b16 {%0,%1,%2,%3}, [%4];"
                 : "=r"(r0), "=r"(r1), "=r"(r2), "=r"(r3) : "r"(addr));
}

__device__ __forceinline__ void mma16816(float* c, const uint32_t* a, const uint32_t* b) {
    asm volatile(
        "mma.sync.aligned.m16n8k16.row.col.f32.f16.f16.f32 "
        "{%0,%1,%2,%3}, {%4,%5,%6,%7}, {%8,%9}, {%0,%1,%2,%3};"
        : "+f"(c[0]), "+f"(c[1]), "+f"(c[2]), "+f"(c[3])
        : "r"(a[0]), "r"(a[1]), "r"(a[2]), "r"(a[3]), "r"(b[0]), "r"(b[1]));
}

__device__ __forceinline__ uint32_t pack_h2(float v0, float v1) {
    __half h0 = __float2half_rn(v0);
    __half h1 = __float2half_rn(v1);
    return ((uint32_t)__half_as_ushort(h1) << 16) | (uint32_t)__half_as_ushort(h0);
}

// ---------------------------------------------------------------------------
// Pure fp16 HMMA GEMM, 4-stage cp.async pipeline (at legacy-HMMA HW floor).
// MODE 0 (layer1): A = x16, B = W1t; epilogue stores h1 fp16.
// MODE 1 (layer2): A = h1,  B = W2t; epilogue fuses sum/max pooling.
// (UNCHANGED — proven correct and at floor.)
// ---------------------------------------------------------------------------
template <int MODE>
__global__ void __launch_bounds__(256, 1)
phi_gemm(const float* __restrict__ bias, int K, int C)
{
    extern __shared__ char dsm[];
    __shared__ float sbias[BN];
    __shared__ float sSum[2][BN], sMax[2][BN];

    const int tid  = threadIdx.x;
    const int lane = tid & 31;
    const int wid  = tid >> 5;
    const int wm   = wid >> 2;     // 0..1
    const int wn   = wid & 3;      // 0..3
    const int rowBlk = blockIdx.y * BM;
    const int colBlk = blockIdx.x * BN;

    const unsigned short* A = (MODE == 0) ? g_x16 : g_h1;
    const unsigned short* Bm = (MODE == 0) ? g_w1t : g_w2t;

    const uint32_t sb = (smem_u32(dsm) + 1023u) & ~1023u;

    if (tid < BN) sbias[tid] = bias[colBlk + tid];

    float acc[4][8][4];
#pragma unroll
    for (int i = 0; i < 4; i++)
#pragma unroll
        for (int j = 0; j < 8; j++)
#pragma unroll
            for (int k = 0; k < 4; k++) acc[i][j][k] = 0.f;

    // ldmatrix per-thread addressing (swizzled 128B rows)
    const int arow = wm * 64 + (lane & 15);
    const uint32_t aRowOff = (uint32_t)arow * 128;
    const uint32_t aXor = ((uint32_t)(arow & 7)) << 4;
    const int brow = wn * 64 + (lane & 15);
    const uint32_t bRowOff = (uint32_t)brow * 128;
    const uint32_t bXor = ((uint32_t)(brow & 7)) << 4;
    const uint32_t csel = ((uint32_t)((lane >> 4) & 1)) << 4;

    auto load_chunk = [&](int stage, int kt) {
        uint32_t st = sb + stage * STG;
#pragma unroll
        for (int l = 0; l < 4; l++) {
            int f = tid + l * 256;
            int r = f >> 3, q = f & 7;
            uint32_t off = (uint32_t)(r * 128) +
                           (((uint32_t)(q * 16)) ^ (((uint32_t)(r & 7)) << 4));
            cp16(st + off, A + (size_t)(rowBlk + r) * K + kt + q * 8);
        }
#pragma unroll
        for (int l = 0; l < 8; l++) {
            int f = tid + l * 256;
            int r = f >> 3, q = f & 7;
            uint32_t off = (uint32_t)(r * 128) +
                           (((uint32_t)(q * 16)) ^ (((uint32_t)(r & 7)) << 4));
            cp16(st + OFFB + off, Bm + (size_t)(colBlk + r) * K + kt + q * 8);
        }
        CP_COMMIT();
    };

    load_chunk(0, 0);
    if (C > 1) load_chunk(1, BK);
    if (C > 2) load_chunk(2, 2 * BK);

    for (int c = 0; c < C; c++) {
        if (c + 2 < C)      { CP_WAIT(2); }
        else if (c + 1 < C) { CP_WAIT(1); }
        else                { CP_WAIT(0); }
        __syncthreads();
        if (c + 3 < C) load_chunk((c + 3) & (NSTAGE - 1), (c + 3) * BK);

        const uint32_t st = sb + (c & (NSTAGE - 1)) * STG;
#pragma unroll
        for (int k16 = 0; k16 < 4; k16++) {
            const uint32_t cb = k16 * 32;
            uint32_t ah[4][4];
#pragma unroll
            for (int mi = 0; mi < 4; mi++) {
                uint32_t aoff = aRowOff + mi * 2048 + ((cb + csel) ^ aXor);
                ldsm_x4(ah[mi][0], ah[mi][1], ah[mi][2], ah[mi][3], st + aoff);
            }
#pragma unroll
            for (int nb = 0; nb < 4; nb++) {
                uint32_t boff = bRowOff + nb * 2048 + ((cb + csel) ^ bXor);
                uint32_t b0, b1, b2, b3;
                ldsm_x4(b0, b1, b2, b3, st + OFFB + boff);
                uint32_t bfr0[2] = {b0, b2};
                uint32_t bfr1[2] = {b1, b3};
#pragma unroll
                for (int mi = 0; mi < 4; mi++) {
                    mma16816(acc[mi][nb * 2],     ah[mi], bfr0);
                    mma16816(acc[mi][nb * 2 + 1], ah[mi], bfr1);
                }
            }
        }
    }

    // ------------------------- epilogue -------------------------
    const int r0base = wm * 64 + (lane >> 2);
    const int n0base = wn * 64 + 2 * (lane & 3);

    if (MODE == 0) {
#pragma unroll
        for (int mi = 0; mi < 4; mi++) {
            int r0 = rowBlk + r0base + mi * 16;
#pragma unroll
            for (int ni = 0; ni < 8; ni++) {
                int nrel = n0base + ni * 8;
                float b0 = sbias[nrel], b1 = sbias[nrel + 1];
                float v00 = fmaxf(acc[mi][ni][0] + b0, 0.f);
                float v01 = fmaxf(acc[mi][ni][1] + b1, 0.f);
                float v10 = fmaxf(acc[mi][ni][2] + b0, 0.f);
                float v11 = fmaxf(acc[mi][ni][3] + b1, 0.f);
                *(uint32_t*)&g_h1[(size_t)r0 * DH + colBlk + nrel] = pack_h2(v00, v01);
                *(uint32_t*)&g_h1[(size_t)(r0 + 8) * DH + colBlk + nrel] = pack_h2(v10, v11);
            }
        }
    } else {
        const int bIdx = rowBlk >> 9;
        float s[8][2], mx[8][2];
#pragma unroll
        for (int ni = 0; ni < 8; ni++) { s[ni][0] = s[ni][1] = 0.f;
                                         mx[ni][0] = mx[ni][1] = 0.f; }
#pragma unroll
        for (int mi = 0; mi < 4; mi++)
#pragma unroll
            for (int ni = 0; ni < 8; ni++) {
                int nrel = n0base + ni * 8;
                float b0 = sbias[nrel], b1 = sbias[nrel + 1];
                float v00 = fmaxf(acc[mi][ni][0] + b0, 0.f);
                float v01 = fmaxf(acc[mi][ni][1] + b1, 0.f);
                float v10 = fmaxf(acc[mi][ni][2] + b0, 0.f);
                float v11 = fmaxf(acc[mi][ni][3] + b1, 0.f);
                s[ni][0] += v00 + v10;  s[ni][1] += v01 + v11;
                mx[ni][0] = fmaxf(mx[ni][0], fmaxf(v00, v10));
                mx[ni][1] = fmaxf(mx[ni][1], fmaxf(v01, v11));
            }
#pragma unroll
        for (int o = 4; o < 32; o <<= 1)
#pragma unroll
            for (int ni = 0; ni < 8; ni++)
#pragma unroll
                for (int j = 0; j < 2; j++) {
                    s[ni][j]  += __shfl_xor_sync(0xffffffffu, s[ni][j], o);
                    mx[ni][j]  = fmaxf(mx[ni][j],
                                       __shfl_xor_sync(0xffffffffu, mx[ni][j], o));
                }
        if ((lane >> 2) == 0) {
#pragma unroll
            for (int ni = 0; ni < 8; ni++)
#pragma unroll
                for (int j = 0; j < 2; j++) {
                    int col = wn * 64 + ni * 8 + 2 * lane + j;
                    sSum[wm][col] = s[ni][j];
                    sMax[wm][col] = mx[ni][j];
                }
        }
        __syncthreads();
        {
            float S = sSum[0][tid] + sSum[1][tid];
            float M = fmaxf(sMax[0][tid], sMax[1][tid]);
            atomicAdd(&g_pooled[bIdx * 2 * DH + colBlk + tid], S);
            atomicMax((int*)&g_pooled[bIdx * 2 * DH + DH + colBlk + tid],
                      __float_as_int(M));
        }
    }
}

// ---------------------------------------------------------------------------
// Fused prep kernel (cvt at 32B/thread: 8192 cvt blocks)
// ---------------------------------------------------------------------------
#define PREP_CVT_BLKS 8192    // MPHI*DIN/8/256 (2 float4 per thread)
#define PREP_Z_BLKS   512
#define PREP_T1_BLKS  512     // (DH/32)*(DIN/32)
#define PREP_T2_BLKS  1024    // (DH/32)*(DH/32)
#define PREP_BLKS (PREP_CVT_BLKS + PREP_Z_BLKS + PREP_T1_BLKS + PREP_T2_BLKS)

__global__ void __launch_bounds__(256)
prep_kernel(const float* __restrict__ x,
            const float* __restrict__ W1,
            const float* __restrict__ W2)
{
    __shared__ float t[32][33];
    const int b = blockIdx.x;
    const int tid = threadIdx.x;

    if (b < PREP_CVT_BLKS) {
        int i = (b * 256 + tid) * 2;               // float4 index (2 per thread)
#pragma unroll
        for (int u = 0; u < 2; u++) {
            float4 v = ((const float4*)x)[i + u];
            uint2 o;
            o.x = pack_h2(v.x, v.y);
            o.y = pack_h2(v.z, v.w);
            ((uint2*)g_x16)[i + u] = o;
        }
        return;
    }
    if (b < PREP_CVT_BLKS + PREP_Z_BLKS) {
        int i = (b - PREP_CVT_BLKS) * 256 + tid;
        if (i < BB * 2 * DH) g_pooled[i] = 0.f;
        if (i < BB * DH) { g_racc1[i] = 0.f; g_racc2[i] = 0.f; }
        return;
    }
    const float* src;
    unsigned short* dst;
    int R, Cn, bb;
    if (b < PREP_CVT_BLKS + PREP_Z_BLKS + PREP_T1_BLKS) {
        bb = b - (PREP_CVT_BLKS + PREP_Z_BLKS);
        src = W1; dst = g_w1t; R = DIN; Cn = DH;
    } else {
        bb = b - (PREP_CVT_BLKS + PREP_Z_BLKS + PREP_T1_BLKS);
        src = W2; dst = g_w2t; R = DH; Cn = DH;
    }
    const int bx = (bb & 31) * 32;
    const int by = (bb >> 5) * 32;
    const int tx = tid & 31, ty = tid >> 5;
#pragma unroll
    for (int i = 0; i < 32; i += 8)
        t[ty + i][tx] = src[(size_t)(by + ty + i) * Cn + bx + tx];
    __syncthreads();
#pragma unroll
    for (int i = 0; i < 32; i += 8) {
        int n = bx + ty + i, k = by + tx;
        dst[(size_t)n * R + k] = __half_as_ushort(__float2half_rn(t[tx][ty + i]));
    }
}

// ---------------------------------------------------------------------------
// rho GEMMs: split-K FFMA, 4x4 register blocking, KS=128 per CTA,
// W tiles double-buffered via cp.async so tile-1's DRAM latency hides under
// tile-0 compute (profile showed rho latency-exposed on the Wr read).
// Dynamic smem: As[2][64][68] + Ws[2][64][68] = 68KB.
// PHASE 0: A = g_pooled (lda 2048) -> g_racc1.  grid (16, 16)
// PHASE 1: A = relu(g_racc1 + br1) on load (lda 1024) -> g_racc2. grid (16, 8)
// ---------------------------------------------------------------------------
template <int PHASE>
__global__ void __launch_bounds__(256)
rho_partial(const float* __restrict__ W, const float* __restrict__ bias_in)
{
    const int lda = (PHASE == 0) ? 2 * DH : DH;
    const float* A = (PHASE == 0) ? (const float*)g_pooled : (const float*)g_racc1;
    float* acc     = (PHASE == 0) ? g_racc1 : g_racc2;

    extern __shared__ float rsm[];
    float* AsB = rsm;                    // [2][64][68]
    float* WsB = rsm + 2 * RHO_TILE;     // [2][64][68]

    const int tid = threadIdx.x;
    const int tx = tid & 15, ty = tid >> 4;    // 16 x 16
    const int col0 = blockIdx.x * 64;
    const int k0 = blockIdx.y * 128;

    // W tile via cp.async (the DRAM-heavy stream)
    auto load_W = [&](int buf, int kbase) {
        float* Wd = WsB + buf * RHO_TILE;
#pragma unroll
        for (int l = 0; l < 4; l++) {
            int f = tid + l * 256;
            int kk = f >> 4, cq = f & 15;
            cp16(smem_u32(&Wd[kk * 68 + cq * 4]),
                 &W[(size_t)(kbase + kk) * DH + col0 + cq * 4]);
        }
        CP_COMMIT();
    };
    // A tile direct (PHASE 1 applies relu(x+bias) on load; A is L2-resident)
    auto load_A = [&](int buf, int kbase) {
        float* Ad = AsB + buf * RHO_TILE;
#pragma unroll
        for (int l = 0; l < 4; l++) {
            int f = tid + l * 256;
            int row = f >> 4, kq = f & 15;
            float4 v = *reinterpret_cast<const float4*>(
                &A[(size_t)row * lda + kbase + kq * 4]);
            if (PHASE == 1) {
                float4 bv = *reinterpret_cast<const float4*>(&bias_in[kbase + kq * 4]);
                v.x = fmaxf(v.x + bv.x, 0.f); v.y = fmaxf(v.y + bv.y, 0.f);
                v.z = fmaxf(v.z + bv.z, 0.f); v.w = fmaxf(v.w + bv.w, 0.f);
            }
            Ad[(kq * 4 + 0) * 68 + row] = v.x;
            Ad[(kq * 4 + 1) * 68 + row] = v.y;
            Ad[(kq * 4 + 2) * 68 + row] = v.z;
            Ad[(kq * 4 + 3) * 68 + row] = v.w;
        }
    };

    // issue both W tile loads first (max MLP), A tiles overlap them
    load_W(0, k0);
    load_W(1, k0 + 64);
    load_A(0, k0);
    load_A(1, k0 + 64);

    float a16[4][4];
#pragma unroll
    for (int i = 0; i < 4; i++)
#pragma unroll
        for (int j = 0; j < 4; j++) a16[i][j] = 0.f;

#pragma unroll
    for (int t = 0; t < 2; t++) {
        if (t == 0) { CP_WAIT(1); } else { CP_WAIT(0); }
        __syncthreads();
        const float* Ad = AsB + t * RHO_TILE;
        const float* Wd = WsB + t * RHO_TILE;
#pragma unroll
        for (int kk = 0; kk < 64; kk++) {
            float4 av = *reinterpret_cast<const float4*>(&Ad[kk * 68 + ty * 4]);
            float4 wv = *reinterpret_cast<const float4*>(&Wd[kk * 68 + tx * 4]);
            float avr[4] = {av.x, av.y, av.z, av.w};
            float wvr[4] = {wv.x, wv.y, wv.z, wv.w};
#pragma unroll
            for (int i = 0; i < 4; i++)
#pragma unroll
                for (int j = 0; j < 4; j++) a16[i][j] += avr[i] * wvr[j];
        }
    }

#pragma unroll
    for (int i = 0; i < 4; i++)
#pragma unroll
        for (int j = 0; j < 4; j++)
            atomicAdd(&acc[(size_t)(ty * 4 + i) * DH + col0 + tx * 4 + j], a16[i][j]);
}

// final: out = relu(g_racc2 + br2)
__global__ void bias_relu_final(const float* __restrict__ b, float* __restrict__ out) {
    int i = blockIdx.x * 256 + threadIdx.x;
    out[i] = fmaxf(g_racc2[i] + b[i & (DH - 1)], 0.f);
}

// ---------------------------------------------------------------------------
// Launch
// ---------------------------------------------------------------------------
extern "C" void kernel_launch(void* const* d_in, const int* in_sizes, int n_in,
                              void* d_out, int out_size)
{
    const float* x   = (const float*)d_in[0];
    const float* W1  = (const float*)d_in[1];
    const float* b1  = (const float*)d_in[2];
    const float* W2  = (const float*)d_in[3];
    const float* b2  = (const float*)d_in[4];
    const float* Wr1 = (const float*)d_in[5];
    const float* br1 = (const float*)d_in[6];
    const float* Wr2 = (const float*)d_in[7];
    const float* br2 = (const float*)d_in[8];
    float* out       = (float*)d_out;

    cudaFuncSetAttribute(phi_gemm<0>, cudaFuncAttributeMaxDynamicSharedMemorySize, DYN_SMEM);
    cudaFuncSetAttribute(phi_gemm<1>, cudaFuncAttributeMaxDynamicSharedMemorySize, DYN_SMEM);
    cudaFuncSetAttribute(rho_partial<0>, cudaFuncAttributeMaxDynamicSharedMemorySize, RHO_SMEM);
    cudaFuncSetAttribute(rho_partial<1>, cudaFuncAttributeMaxDynamicSharedMemorySize, RHO_SMEM);

    // fused prep: cvt x, zero accumulators, transpose+cvt W1/W2
    prep_kernel<<<PREP_BLKS, 256>>>(x, W1, W2);

    // phi layer 1: h1 = relu(x @ W1 + b1) -> fp16
    phi_gemm<0><<<dim3(DH / BN, MPHI / BM), 256, DYN_SMEM>>>(b1, DIN, DIN / BK);
    // phi layer 2 + fused sum/max pooling
    phi_gemm<1><<<dim3(DH / BN, MPHI / BM), 256, DYN_SMEM>>>(b2, DH, DH / BK);

    // rho (fp32 exact): 64x64 tiles, KS=128, W double-buffered
    rho_partial<0><<<dim3(DH / 64, DH / 64), 256, RHO_SMEM>>>(Wr1, nullptr);  // 256 CTAs
    rho_partial<1><<<dim3(DH / 64, DH / 128), 256, RHO_SMEM>>>(Wr2, br1);     // 128 CTAs
    bias_relu_final<<<BB * DH / 256, 256>>>(br2, out);
}

// round 16
// speedup vs baseline: 1.0890x; 1.0845x over previous
#include <cuda_runtime.h>
#include <cuda_fp16.h>
#include <cstdint>

// ---------------------------------------------------------------------------
// Problem dims
// ---------------------------------------------------------------------------
#define BB   64
#define NSET 512
#define DIN  512
#define DH   1024
#define MPHI (BB * NSET)   // 32768

// phi tiling: CTA 128x128, BK=64, warp tile 64x32 (2x4 warps), 2 stages,
// 2 CTAs/SM (occupancy experiment: 16 warps/SM vs previous 8).
#define BM 128
#define BN 128
#define BK 64
#define OFFB 16384
#define STG  32768
#define DYN_SMEM (2 * STG + 1024)

// rho smem: 2 bufs x (As 64x68 + Ws 64x68) floats
#define RHO_TILE (64 * 68)
#define RHO_SMEM (4 * RHO_TILE * (int)sizeof(float))   // 69632 B

// ---------------------------------------------------------------------------
// Device scratch (fp16 words as unsigned short)
// ---------------------------------------------------------------------------
__device__ unsigned short g_x16[(size_t)MPHI * DIN];     // x as fp16
__device__ unsigned short g_w1t[(size_t)DH * DIN];       // W1^T [N,K] fp16
__device__ unsigned short g_w2t[(size_t)DH * DH];        // W2^T [N,K] fp16
__device__ unsigned short g_h1[(size_t)MPHI * DH];       // h1 fp16
__device__ float g_pooled[BB * 2 * DH];
__device__ float g_racc1[BB * DH];
__device__ float g_racc2[BB * DH];

// ---------------------------------------------------------------------------
// PTX helpers
// ---------------------------------------------------------------------------
__device__ __forceinline__ uint32_t smem_u32(const void* p) {
    uint32_t a;
    asm("{ .reg .u64 t; cvta.to.shared.u64 t, %1; cvt.u32.u64 %0, t; }"
        : "=r"(a) : "l"(p));
    return a;
}

__device__ __forceinline__ void cp16(uint32_t dst, const void* src) {
    asm volatile("cp.async.cg.shared.global [%0], [%1], 16;"
                 :: "r"(dst), "l"(src));
}
#define CP_COMMIT() asm volatile("cp.async.commit_group;" ::: "memory")
#define CP_WAIT(n)  asm volatile("cp.async.wait_group %0;" :: "n"(n) : "memory")

__device__ __forceinline__ void ldsm_x4(uint32_t& r0, uint32_t& r1,
                                        uint32_t& r2, uint32_t& r3, uint32_t addr) {
    asm volatile("ldmatrix.sync.aligned.m8n8.x4.shared.b16 {%0,%1,%2,%3}, [%4];"
                 : "=r"(r0), "=r"(r1), "=r"(r2), "=r"(r3) : "r"(addr));
}

__device__ __forceinline__ void mma16816(float* c, const uint32_t* a, const uint32_t* b) {
    asm volatile(
        "mma.sync.aligned.m16n8k16.row.col.f32.f16.f16.f32 "
        "{%0,%1,%2,%3}, {%4,%5,%6,%7}, {%8,%9}, {%0,%1,%2,%3};"
        : "+f"(c[0]), "+f"(c[1]), "+f"(c[2]), "+f"(c[3])
        : "r"(a[0]), "r"(a[1]), "r"(a[2]), "r"(a[3]), "r"(b[0]), "r"(b[1]));
}

__device__ __forceinline__ uint32_t pack_h2(float v0, float v1) {
    __half h0 = __float2half_rn(v0);
    __half h1 = __float2half_rn(v1);
    return ((uint32_t)__half_as_ushort(h1) << 16) | (uint32_t)__half_as_ushort(h0);
}

// ---------------------------------------------------------------------------
// Pure fp16 HMMA GEMM, 2-stage double buffer, 2 CTAs/SM.
// MODE 0 (layer1): A = x16, B = W1t; epilogue stores h1 fp16.
// MODE 1 (layer2): A = h1,  B = W2t; epilogue fuses sum/max pooling.
// ---------------------------------------------------------------------------
template <int MODE>
__global__ void __launch_bounds__(256, 2)
phi_gemm(const float* __restrict__ bias, int K, int C)
{
    extern __shared__ char dsm[];
    __shared__ float sbias[BN];
    __shared__ float sSum[2][BN], sMax[2][BN];

    const int tid  = threadIdx.x;
    const int lane = tid & 31;
    const int wid  = tid >> 5;
    const int wm   = wid >> 2;     // 0..1
    const int wn   = wid & 3;      // 0..3
    const int rowBlk = blockIdx.y * BM;
    const int colBlk = blockIdx.x * BN;

    const unsigned short* A  = (MODE == 0) ? g_x16 : g_h1;
    const unsigned short* Bm = (MODE == 0) ? g_w1t : g_w2t;

    const uint32_t sb = (smem_u32(dsm) + 1023u) & ~1023u;

    if (tid < BN) sbias[tid] = bias[colBlk + tid];

    float acc[4][4][4];
#pragma unroll
    for (int i = 0; i < 4; i++)
#pragma unroll
        for (int j = 0; j < 4; j++)
#pragma unroll
            for (int k = 0; k < 4; k++) acc[i][j][k] = 0.f;

    // ldmatrix per-thread addressing (swizzled 128B rows)
    const int arow = wm * 64 + (lane & 15);
    const uint32_t aRowOff = (uint32_t)arow * 128;
    const uint32_t aXor = ((uint32_t)(arow & 7)) << 4;
    const int brow = wn * 32 + (lane & 15);
    const uint32_t bRowOff = (uint32_t)brow * 128;
    const uint32_t bXor = ((uint32_t)(brow & 7)) << 4;
    const uint32_t csel = ((uint32_t)((lane >> 4) & 1)) << 4;

    // stage loader: A 128x64 (16KB) + B 128x64 (16KB)
    auto load_chunk = [&](int stage, int kt) {
        uint32_t st = sb + stage * STG;
#pragma unroll
        for (int l = 0; l < 4; l++) {
            int f = tid + l * 256;
            int r = f >> 3, q = f & 7;
            uint32_t off = (uint32_t)(r * 128) +
                           (((uint32_t)(q * 16)) ^ (((uint32_t)(r & 7)) << 4));
            cp16(st + off, A + (size_t)(rowBlk + r) * K + kt + q * 8);
            cp16(st + OFFB + off, Bm + (size_t)(colBlk + r) * K + kt + q * 8);
        }
        CP_COMMIT();
    };

    load_chunk(0, 0);
    if (C > 1) load_chunk(1, BK);

    for (int c = 0; c < C; c++) {
        if (c + 1 < C) { CP_WAIT(1); } else { CP_WAIT(0); }
        __syncthreads();

        const uint32_t st = sb + (c & 1) * STG;
#pragma unroll
        for (int k16 = 0; k16 < 4; k16++) {
            const uint32_t cb = k16 * 32;
            uint32_t ah[4][4];
#pragma unroll
            for (int mi = 0; mi < 4; mi++) {
                uint32_t aoff = aRowOff + mi * 2048 + ((cb + csel) ^ aXor);
                ldsm_x4(ah[mi][0], ah[mi][1], ah[mi][2], ah[mi][3], st + aoff);
            }
#pragma unroll
            for (int nb = 0; nb < 2; nb++) {
                uint32_t boff = bRowOff + nb * 2048 + ((cb + csel) ^ bXor);
                uint32_t b0, b1, b2, b3;
                ldsm_x4(b0, b1, b2, b3, st + OFFB + boff);
                uint32_t bfr0[2] = {b0, b2};
                uint32_t bfr1[2] = {b1, b3};
#pragma unroll
                for (int mi = 0; mi < 4; mi++) {
                    mma16816(acc[mi][nb * 2],     ah[mi], bfr0);
                    mma16816(acc[mi][nb * 2 + 1], ah[mi], bfr1);
                }
            }
        }
        // refill the stage just consumed (needs all warps done with it)
        if (c + 2 < C) {
            __syncthreads();
            load_chunk(c & 1, (c + 2) * BK);
        }
    }

    // ------------------------- epilogue -------------------------
    const int r0base = wm * 64 + (lane >> 2);
    const int n0base = wn * 32 + 2 * (lane & 3);

    if (MODE == 0) {
#pragma unroll
        for (int mi = 0; mi < 4; mi++) {
            int r0 = rowBlk + r0base + mi * 16;
#pragma unroll
            for (int ni = 0; ni < 4; ni++) {
                int nrel = n0base + ni * 8;
                float b0 = sbias[nrel], b1 = sbias[nrel + 1];
                float v00 = fmaxf(acc[mi][ni][0] + b0, 0.f);
                float v01 = fmaxf(acc[mi][ni][1] + b1, 0.f);
                float v10 = fmaxf(acc[mi][ni][2] + b0, 0.f);
                float v11 = fmaxf(acc[mi][ni][3] + b1, 0.f);
                *(uint32_t*)&g_h1[(size_t)r0 * DH + colBlk + nrel] = pack_h2(v00, v01);
                *(uint32_t*)&g_h1[(size_t)(r0 + 8) * DH + colBlk + nrel] = pack_h2(v10, v11);
            }
        }
    } else {
        const int bIdx = rowBlk >> 9;   // 512 rows per batch, 128 | 512
        float s[4][2], mx[4][2];
#pragma unroll
        for (int ni = 0; ni < 4; ni++) { s[ni][0] = s[ni][1] = 0.f;
                                         mx[ni][0] = mx[ni][1] = 0.f; }
#pragma unroll
        for (int mi = 0; mi < 4; mi++)
#pragma unroll
            for (int ni = 0; ni < 4; ni++) {
                int nrel = n0base + ni * 8;
                float b0 = sbias[nrel], b1 = sbias[nrel + 1];
                float v00 = fmaxf(acc[mi][ni][0] + b0, 0.f);
                float v01 = fmaxf(acc[mi][ni][1] + b1, 0.f);
                float v10 = fmaxf(acc[mi][ni][2] + b0, 0.f);
                float v11 = fmaxf(acc[mi][ni][3] + b1, 0.f);
                s[ni][0] += v00 + v10;  s[ni][1] += v01 + v11;
                mx[ni][0] = fmaxf(mx[ni][0], fmaxf(v00, v10));
                mx[ni][1] = fmaxf(mx[ni][1], fmaxf(v01, v11));
            }
#pragma unroll
        for (int o = 4; o < 32; o <<= 1)
#pragma unroll
            for (int ni = 0; ni < 4; ni++)
#pragma unroll
                for (int j = 0; j < 2; j++) {
                    s[ni][j]  += __shfl_xor_sync(0xffffffffu, s[ni][j], o);
                    mx[ni][j]  = fmaxf(mx[ni][j],
                                       __shfl_xor_sync(0xffffffffu, mx[ni][j], o));
                }
        if ((lane >> 2) == 0) {
#pragma unroll
            for (int ni = 0; ni < 4; ni++)
#pragma unroll
                for (int j = 0; j < 2; j++) {
                    int col = wn * 32 + ni * 8 + 2 * lane + j;
                    sSum[wm][col] = s[ni][j];
                    sMax[wm][col] = mx[ni][j];
                }
        }
        __syncthreads();
        if (tid < BN) {
            float S = sSum[0][tid] + sSum[1][tid];
            float M = fmaxf(sMax[0][tid], sMax[1][tid]);
            atomicAdd(&g_pooled[bIdx * 2 * DH + colBlk + tid], S);
            atomicMax((int*)&g_pooled[bIdx * 2 * DH + DH + colBlk + tid],
                      __float_as_int(M));
        }
    }
}

// ---------------------------------------------------------------------------
// Fused prep kernel (cvt at 32B/thread: 8192 cvt blocks)
// ---------------------------------------------------------------------------
#define PREP_CVT_BLKS 8192    // MPHI*DIN/8/256 (2 float4 per thread)
#define PREP_Z_BLKS   512
#define PREP_T1_BLKS  512     // (DH/32)*(DIN/32)
#define PREP_T2_BLKS  1024    // (DH/32)*(DH/32)
#define PREP_BLKS (PREP_CVT_BLKS + PREP_Z_BLKS + PREP_T1_BLKS + PREP_T2_BLKS)

__global__ void __launch_bounds__(256)
prep_kernel(const float* __restrict__ x,
            const float* __restrict__ W1,
            const float* __restrict__ W2)
{
    __shared__ float t[32][33];
    const int b = blockIdx.x;
    const int tid = threadIdx.x;

    if (b < PREP_CVT_BLKS) {
        int i = (b * 256 + tid) * 2;               // float4 index (2 per thread)
#pragma unroll
        for (int u = 0; u < 2; u++) {
            float4 v = ((const float4*)x)[i + u];
            uint2 o;
            o.x = pack_h2(v.x, v.y);
            o.y = pack_h2(v.z, v.w);
            ((uint2*)g_x16)[i + u] = o;
        }
        return;
    }
    if (b < PREP_CVT_BLKS + PREP_Z_BLKS) {
        int i = (b - PREP_CVT_BLKS) * 256 + tid;
        if (i < BB * 2 * DH) g_pooled[i] = 0.f;
        if (i < BB * DH) { g_racc1[i] = 0.f; g_racc2[i] = 0.f; }
        return;
    }
    const float* src;
    unsigned short* dst;
    int R, Cn, bb;
    if (b < PREP_CVT_BLKS + PREP_Z_BLKS + PREP_T1_BLKS) {
        bb = b - (PREP_CVT_BLKS + PREP_Z_BLKS);
        src = W1; dst = g_w1t; R = DIN; Cn = DH;
    } else {
        bb = b - (PREP_CVT_BLKS + PREP_Z_BLKS + PREP_T1_BLKS);
        src = W2; dst = g_w2t; R = DH; Cn = DH;
    }
    const int bx = (bb & 31) * 32;
    const int by = (bb >> 5) * 32;
    const int tx = tid & 31, ty = tid >> 5;
#pragma unroll
    for (int i = 0; i < 32; i += 8)
        t[ty + i][tx] = src[(size_t)(by + ty + i) * Cn + bx + tx];
    __syncthreads();
#pragma unroll
    for (int i = 0; i < 32; i += 8) {
        int n = bx + ty + i, k = by + tx;
        dst[(size_t)n * R + k] = __half_as_ushort(__float2half_rn(t[tx][ty + i]));
    }
}

// ---------------------------------------------------------------------------
// rho GEMMs (UNCHANGED from round 15 best): split-K FFMA, 4x4 register
// blocking, KS=128 per CTA, W double-buffered via cp.async.
// ---------------------------------------------------------------------------
template <int PHASE>
__global__ void __launch_bounds__(256)
rho_partial(const float* __restrict__ W, const float* __restrict__ bias_in)
{
    const int lda = (PHASE == 0) ? 2 * DH : DH;
    const float* A = (PHASE == 0) ? (const float*)g_pooled : (const float*)g_racc1;
    float* acc     = (PHASE == 0) ? g_racc1 : g_racc2;

    extern __shared__ float rsm[];
    float* AsB = rsm;                    // [2][64][68]
    float* WsB = rsm + 2 * RHO_TILE;     // [2][64][68]

    const int tid = threadIdx.x;
    const int tx = tid & 15, ty = tid >> 4;    // 16 x 16
    const int col0 = blockIdx.x * 64;
    const int k0 = blockIdx.y * 128;

    auto load_W = [&](int buf, int kbase) {
        float* Wd = WsB + buf * RHO_TILE;
#pragma unroll
        for (int l = 0; l < 4; l++) {
            int f = tid + l * 256;
            int kk = f >> 4, cq = f & 15;
            cp16(smem_u32(&Wd[kk * 68 + cq * 4]),
                 &W[(size_t)(kbase + kk) * DH + col0 + cq * 4]);
        }
        CP_COMMIT();
    };
    auto load_A = [&](int buf, int kbase) {
        float* Ad = AsB + buf * RHO_TILE;
#pragma unroll
        for (int l = 0; l < 4; l++) {
            int f = tid + l * 256;
            int row = f >> 4, kq = f & 15;
            float4 v = *reinterpret_cast<const float4*>(
                &A[(size_t)row * lda + kbase + kq * 4]);
            if (PHASE == 1) {
                float4 bv = *reinterpret_cast<const float4*>(&bias_in[kbase + kq * 4]);
                v.x = fmaxf(v.x + bv.x, 0.f); v.y = fmaxf(v.y + bv.y, 0.f);
                v.z = fmaxf(v.z + bv.z, 0.f); v.w = fmaxf(v.w + bv.w, 0.f);
            }
            Ad[(kq * 4 + 0) * 68 + row] = v.x;
            Ad[(kq * 4 + 1) * 68 + row] = v.y;
            Ad[(kq * 4 + 2) * 68 + row] = v.z;
            Ad[(kq * 4 + 3) * 68 + row] = v.w;
        }
    };

    load_W(0, k0);
    load_W(1, k0 + 64);
    load_A(0, k0);
    load_A(1, k0 + 64);

    float a16[4][4];
#pragma unroll
    for (int i = 0; i < 4; i++)
#pragma unroll
        for (int j = 0; j < 4; j++) a16[i][j] = 0.f;

#pragma unroll
    for (int t = 0; t < 2; t++) {
        if (t == 0) { CP_WAIT(1); } else { CP_WAIT(0); }
        __syncthreads();
        const float* Ad = AsB + t * RHO_TILE;
        const float* Wd = WsB + t * RHO_TILE;
#pragma unroll
        for (int kk = 0; kk < 64; kk++) {
            float4 av = *reinterpret_cast<const float4*>(&Ad[kk * 68 + ty * 4]);
            float4 wv = *reinterpret_cast<const float4*>(&Wd[kk * 68 + tx * 4]);
            float avr[4] = {av.x, av.y, av.z, av.w};
            float wvr[4] = {wv.x, wv.y, wv.z, wv.w};
#pragma unroll
            for (int i = 0; i < 4; i++)
#pragma unroll
                for (int j = 0; j < 4; j++) a16[i][j] += avr[i] * wvr[j];
        }
    }

#pragma unroll
    for (int i = 0; i < 4; i++)
#pragma unroll
        for (int j = 0; j < 4; j++)
            atomicAdd(&acc[(size_t)(ty * 4 + i) * DH + col0 + tx * 4 + j], a16[i][j]);
}

// final: out = relu(g_racc2 + br2)
__global__ void bias_relu_final(const float* __restrict__ b, float* __restrict__ out) {
    int i = blockIdx.x * 256 + threadIdx.x;
    out[i] = fmaxf(g_racc2[i] + b[i & (DH - 1)], 0.f);
}

// ---------------------------------------------------------------------------
// Launch
// ---------------------------------------------------------------------------
extern "C" void kernel_launch(void* const* d_in, const int* in_sizes, int n_in,
                              void* d_out, int out_size)
{
    const float* x   = (const float*)d_in[0];
    const float* W1  = (const float*)d_in[1];
    const float* b1  = (const float*)d_in[2];
    const float* W2  = (const float*)d_in[3];
    const float* b2  = (const float*)d_in[4];
    const float* Wr1 = (const float*)d_in[5];
    const float* br1 = (const float*)d_in[6];
    const float* Wr2 = (const float*)d_in[7];
    const float* br2 = (const float*)d_in[8];
    float* out       = (float*)d_out;

    cudaFuncSetAttribute(phi_gemm<0>, cudaFuncAttributeMaxDynamicSharedMemorySize, DYN_SMEM);
    cudaFuncSetAttribute(phi_gemm<1>, cudaFuncAttributeMaxDynamicSharedMemorySize, DYN_SMEM);
    cudaFuncSetAttribute(rho_partial<0>, cudaFuncAttributeMaxDynamicSharedMemorySize, RHO_SMEM);
    cudaFuncSetAttribute(rho_partial<1>, cudaFuncAttributeMaxDynamicSharedMemorySize, RHO_SMEM);

    // fused prep: cvt x, zero accumulators, transpose+cvt W1/W2
    prep_kernel<<<PREP_BLKS, 256>>>(x, W1, W2);

    // phi layer 1: h1 = relu(x @ W1 + b1) -> fp16    grid (8, 256)
    phi_gemm<0><<<dim3(DH / BN, MPHI / BM), 256, DYN_SMEM>>>(b1, DIN, DIN / BK);
    // phi layer 2 + fused sum/max pooling             grid (8, 256)
    phi_gemm<1><<<dim3(DH / BN, MPHI / BM), 256, DYN_SMEM>>>(b2, DH, DH / BK);

    // rho (fp32 exact): 64x64 tiles, KS=128, W double-buffered
    rho_partial<0><<<dim3(DH / 64, DH / 64), 256, RHO_SMEM>>>(Wr1, nullptr);  // 256 CTAs
    rho_partial<1><<<dim3(DH / 64, DH / 128), 256, RHO_SMEM>>>(Wr2, br1);     // 128 CTAs
    bias_relu_final<<<BB * DH / 256, 256>>>(br2, out);
}